// round 14
// baseline (speedup 1.0000x reference)
#include <cuda_runtime.h>

typedef unsigned long long ull;

#define C_DIM 1024
#define TPB   128
#define TILE_R 64
#define PAD  68            // row stride (floats); %4==0 for LDS.128 alignment

// smem arena layout (floats)
#define SM_X   0                        // [128][PAD] RAW x transposed: k 0..63 = ht, 64..127 = kc
#define SM_WD  (128*PAD)                // [64][64] weight tile
#define SM_B1  (SM_WD + 4096)
#define SM_B2  (SM_B1 + 64*PAD)
#define SM_B3  (SM_B2 + 64*PAD)
#define SM_TOT (SM_B3 + 64*PAD)         // 25856 floats = 103424 B  -> 2 blocks/SM

__device__ float g_adj[2 * C_DIM];

__device__ __forceinline__ float4 ldg4(const float* p) {
    return __ldg(reinterpret_cast<const float4*>(p));
}
__device__ __forceinline__ float clipf(float v, float lo, float hi) {
    return fminf(fmaxf(v, lo), hi);
}
__device__ __forceinline__ float sigm(float x) { return 1.f / (1.f + expf(-x)); }

__device__ __forceinline__ void ffma2(ull& d, ull a, ull b) {
    asm("fma.rn.f32x2 %0, %1, %2, %0;" : "+l"(d) : "l"(a), "l"(b));
}
__device__ __forceinline__ ull pk(float x, float y) {
    ull v; asm("mov.b64 %0, {%1, %2};" : "=l"(v) : "f"(x), "f"(y)); return v;
}
__device__ __forceinline__ float2 upk(ull v) {
    float2 r; asm("mov.b64 {%0, %1}, %2;" : "=f"(r.x), "=f"(r.y) : "l"(v)); return r;
}

// ---------------------------------------------------------------------------
// adj pre-kernel
// ---------------------------------------------------------------------------
__global__ void gkt_adj(const int* __restrict__ qt, const float* __restrict__ onehot,
                        const float* __restrict__ graphs) {
    __shared__ int nz[C_DIM];
    __shared__ int wcnt[32];
    __shared__ int woff[33];
    const int t = threadIdx.x, wid = t >> 5, lane = t & 31;
    const int q0 = qt[0];
    const bool on = (onehot[(long)q0 * C_DIM + t] > 0.5f);
    unsigned bal = __ballot_sync(0xffffffffu, on);
    if (lane == 0) wcnt[wid] = __popc(bal);
    __syncthreads();
    if (t == 0) { int s = 0; for (int w = 0; w < 32; ++w) { woff[w] = s; s += wcnt[w]; } woff[32] = s; }
    __syncthreads();
    if (on) nz[woff[wid] + __popc(bal & ((1u << lane) - 1u))] = t;
    __syncthreads();
    const int n = woff[32];
    const float denom = fmaxf((float)n, 1.f);
#pragma unroll
    for (int k = 0; k < 2; ++k) {
        float s = 0.f;
        for (int idx = 0; idx < n; ++idx)
            s += graphs[k * C_DIM * C_DIM + nz[idx] * C_DIM + t];
        g_adj[k * C_DIM + t] = clipf(s / denom, -5.f, 5.f);
    }
}

// ---------------------------------------------------------------------------
// helpers
// ---------------------------------------------------------------------------

// Stage a 64x64 weight tile into WD, natural layout (row = 64 floats).
__device__ __forceinline__ void stage_w(float* __restrict__ WD, const float* __restrict__ src,
                                        int rstride, int t) {
#pragma unroll
    for (int i = t; i < 64 * 16; i += TPB) {
        int kk = i >> 4, o4 = i & 15;
        *reinterpret_cast<float4*>(WD + kk * 64 + o4 * 4) = ldg4(src + kk * rstride + o4 * 4);
    }
}

// acc += A(4 rows) x W(8 outs): per k-step 1 LDS.128 (rows) + 2 LDS.128 (weights) + 16 FFMA2.
template<bool CLIP>
__device__ __forceinline__ void gemm4(const float* __restrict__ A, const float* __restrict__ WD,
                                      int ty, int tx, ull acc[16]) {
    const float* Ab = A + ty * 4;
    const ulonglong2* Wb = reinterpret_cast<const ulonglong2*>(WD) + tx;   // row = 16 u2
#pragma unroll 4
    for (int kk = 0; kk < 64; ++kk) {
        float4 av = *reinterpret_cast<const float4*>(Ab + kk * PAD);
        if (CLIP) {
            av.x = clipf(av.x, -5.f, 5.f); av.y = clipf(av.y, -5.f, 5.f);
            av.z = clipf(av.z, -5.f, 5.f); av.w = clipf(av.w, -5.f, 5.f);
        }
        ull ad[4] = { pk(av.x, av.x), pk(av.y, av.y), pk(av.z, av.z), pk(av.w, av.w) };
        ulonglong2 w0 = Wb[kk * 16];        // floats 4tx .. 4tx+3
        ulonglong2 w1 = Wb[kk * 16 + 8];    // floats 32+4tx .. 32+4tx+3
#pragma unroll
        for (int r = 0; r < 4; ++r) {
            ffma2(acc[r * 4 + 0], ad[r], w0.x);
            ffma2(acc[r * 4 + 1], ad[r], w0.y);
            ffma2(acc[r * 4 + 2], ad[r], w1.x);
            ffma2(acc[r * 4 + 3], ad[r], w1.y);
        }
    }
}

__device__ __forceinline__ void init_bias(ull acc[16], const float* __restrict__ b1p,
                                          const float* __restrict__ b2p, int tx) {
#pragma unroll
    for (int g = 0; g < 2; ++g)
#pragma unroll
    for (int p = 0; p < 2; ++p) {
        int o = 4 * tx + 32 * g + 2 * p;
        float vx = __ldg(b1p + o), vy = __ldg(b1p + o + 1);
        if (b2p) { vx += __ldg(b2p + o); vy += __ldg(b2p + o + 1); }
        ull pv = pk(vx, vy);
        acc[g * 2 + p] = pv; acc[4 + g * 2 + p] = pv;
        acc[8 + g * 2 + p] = pv; acc[12 + g * 2 + p] = pv;
    }
}

// variadic so commas inside the body survive preprocessing
#define EPI_LOOP(...)                                                          \
    _Pragma("unroll")                                                          \
    for (int r = 0; r < 4; ++r) {                                              \
        int row = ty * 4 + r;                                                  \
        _Pragma("unroll")                                                      \
        for (int g = 0; g < 2; ++g)                                            \
        _Pragma("unroll")                                                      \
        for (int p = 0; p < 2; ++p) {                                          \
            int o = 4 * tx + 32 * g + 2 * p;                                   \
            float2 v = upk(acc[r * 4 + g * 2 + p]);                            \
            __VA_ARGS__                                                        \
        }                                                                      \
    }

// sync; stage next weight tile; sync
#define RESTAGE(SRC, RS)                                                       \
    __syncthreads();                                                           \
    stage_w(WD, (SRC), (RS), t);                                               \
    __syncthreads();

// ---------------------------------------------------------------------------
// fused main kernel: 64 rows/block, 128 threads, 2 blocks/SM
// ---------------------------------------------------------------------------
__global__ __launch_bounds__(TPB, 2) void gkt_main(
    const int*   __restrict__ qt,     const float* __restrict__ ht,
    const float* __restrict__ onehot, const float* __restrict__ kc,
    const float* __restrict__ nw_ptr,
    const float* __restrict__ Ws1, const float* __restrict__ bs1,
    const float* __restrict__ Ws2, const float* __restrict__ bs2,
    const float* __restrict__ Wn1, const float* __restrict__ bn1,
    const float* __restrict__ Wn2, const float* __restrict__ bn2,
    const float* __restrict__ ea_w,
    const float* __restrict__ We,  const float* __restrict__ be,
    const float* __restrict__ Wa,  const float* __restrict__ ba,
    const float* __restrict__ W_ih, const float* __restrict__ b_ih,
    const float* __restrict__ W_hh, const float* __restrict__ b_hh,
    const float* __restrict__ Wp,  const float* __restrict__ bp,
    float* __restrict__ out)
{
    extern __shared__ float sm[];
    float* X   = sm + SM_X;             // raw [ht | kc], transposed
    float* XH  = sm + SM_X;             // alias: k rows 0..63 = raw ht
    float* WD  = sm + SM_WD;
    float* B1  = sm + SM_B1;
    float* B2  = sm + SM_B2;
    float* B3  = sm + SM_B3;
    float* B4  = sm + SM_X + 64 * PAD;  // kc region, dead after fix-up
    float* tmp = B3;                    // fix-up scratch (B3 unused until u7)
    int*   mlist = (int*)(B3 + 64);
    int*   mcnt  = (int*)(B3 + 192);

    const int t  = threadIdx.x;
    const int tx = t & 7, ty = t >> 3;        // rows = ty*4 .. ty*4+3 (ty 0..15)
    const int row0 = blockIdx.x * TILE_R;
    const int b  = row0 >> 10;
    const int c0 = row0 & (C_DIM - 1);
    const int q  = __ldg(&qt[b]);

    ull acc[16];
    const float wcl = clipf(__ldg(nw_ptr), 0.1f, 0.9f);

    // ---- prologue: stage raw X + first weight tile ----
#pragma unroll
    for (int i = t; i < TILE_R * 64; i += TPB) {
        int row = i >> 6, k = i & 63;
        X[k * PAD + row]        = ht[(row0 + row) * 64 + k];
        X[(64 + k) * PAD + row] = kc[(c0 + row) * 64 + k];
    }
    stage_w(WD, Wn1 + 128 * 64, 64, t);
    __syncthreads();

    // ===== u0: X_lo @ Wn1[0]_lo =====
    init_bias(acc, bn1, nullptr, tx);
    gemm4<true>(X, WD, ty, tx, acc);
    RESTAGE(Wn1 + 192 * 64, 64)

    // ===== u1: X_hi @ Wn1[0]_hi -> B1 relu =====
    gemm4<true>(X + 64 * PAD, WD, ty, tx, acc);
    EPI_LOOP(
        B1[o * PAD + row]       = fmaxf(v.x, 0.f);
        B1[(o + 1) * PAD + row] = fmaxf(v.y, 0.f);
    )
    RESTAGE(Wn2, 64)

    // ===== u2: B1 @ Wn2[0] -> B2 = nf0 =====
    init_bias(acc, bn2, nullptr, tx);
    gemm4<false>(B1, WD, ty, tx, acc);
    EPI_LOOP(
        float a0 = __ldg(&g_adj[c0 + row]);
        float nb0x = fminf(fmaxf(v.x, 0.f), 5.f);
        float nb0y = fminf(fmaxf(v.y, 0.f), 5.f);
        B2[o * PAD + row]       = clipf(a0 * nb0x, -5.f, 5.f);
        B2[(o + 1) * PAD + row] = clipf(a0 * nb0y, -5.f, 5.f);
    )
    RESTAGE(Wn1 + 256 * 64 + 128 * 64, 64)

    // ===== u3: X_lo @ Wn1[1]_lo =====
    init_bias(acc, bn1 + 64, nullptr, tx);
    gemm4<true>(X, WD, ty, tx, acc);
    RESTAGE(Wn1 + 256 * 64 + 192 * 64, 64)

    // ===== u4: X_hi @ Wn1[1]_hi -> B1 relu =====
    gemm4<true>(X + 64 * PAD, WD, ty, tx, acc);
    EPI_LOOP(
        B1[o * PAD + row]       = fmaxf(v.x, 0.f);
        B1[(o + 1) * PAD + row] = fmaxf(v.y, 0.f);
    )
    RESTAGE(Wn2 + 64 * 64, 64)

    // ===== u5: B1 @ Wn2[1] -> B2 = nf =====
    init_bias(acc, bn2 + 64, nullptr, tx);
    gemm4<false>(B1, WD, ty, tx, acc);
    EPI_LOOP(
        float a1 = __ldg(&g_adj[C_DIM + c0 + row]);
        float nb1x = fminf(fmaxf(v.x, 0.f), 5.f);
        float nb1y = fminf(fmaxf(v.y, 0.f), 5.f);
        float nf0x = B2[o * PAD + row];
        float nf0y = B2[(o + 1) * PAD + row];
        B2[o * PAD + row]       = clipf(wcl * nf0x + (1.f - wcl) * a1 * nb1x, -5.f, 5.f);
        B2[(o + 1) * PAD + row] = clipf(wcl * nf0y + (1.f - wcl) * a1 * nb1y, -5.f, 5.f);
    )
    __syncthreads();

    // ===== masked-row self-MLP fix-up (scratch in B3) =====
    if (t == 0) *mcnt = 0;
    __syncthreads();
    if (t < TILE_R) {
        float m = __ldg(&onehot[(long)q * C_DIM + c0 + t]);
        if (m > 0.5f) { int pos = atomicAdd(mcnt, 1); mlist[pos] = t; }
    }
    __syncthreads();
    const int nm = *mcnt;
    for (int idx = 0; idx < nm; ++idx) {
        int row = mlist[idx];
        if (t < 64) {
            float a = __ldg(bs1 + t);
            for (int k = 0; k < 128; ++k) a += X[k * PAD + row] * __ldg(Ws1 + k * 64 + t);
            tmp[t] = fmaxf(a, 0.f);
        }
        __syncthreads();
        if (t < 64) {
            float a = __ldg(bs2 + t);
            for (int k = 0; k < 64; ++k) a += tmp[k] * __ldg(Ws2 + k * 64 + t);
            B2[t * PAD + row] = clipf(fmaxf(a, 0.f), -10.f, 10.f);
        }
        __syncthreads();
    }
    // B2 = m_next (mn)
    stage_w(WD, We, 64, t);
    __syncthreads();

    // ===== u6: B2 @ We -> B1 = sigE =====
    init_bias(acc, be, nullptr, tx);
    gemm4<false>(B2, WD, ty, tx, acc);
    EPI_LOOP(
        B1[o * PAD + row]       = sigm(v.x);
        B1[(o + 1) * PAD + row] = sigm(v.y);
    )
    RESTAGE(Wa, 64)

    // ===== u7: B2 @ Wa -> B3 = res =====
    init_bias(acc, ba, nullptr, tx);
    gemm4<false>(B2, WD, ty, tx, acc);
    EPI_LOOP(
        float gg = __ldg(&ea_w[c0 + row]);
        float mnx = B2[o * PAD + row];
        float sgx = B1[o * PAD + row];
        float mny = B2[(o + 1) * PAD + row];
        float sgy = B1[(o + 1) * PAD + row];
        B3[o * PAD + row]       = mnx - gg * sgx * mnx + gg * tanhf(v.x);
        B3[(o + 1) * PAD + row] = mny - gg * sgy * mny + gg * tanhf(v.y);
    )
    RESTAGE(W_ih, 192)

    // ===== u8: B3 @ W_ih_r =====
    init_bias(acc, b_ih, b_hh, tx);
    gemm4<false>(B3, WD, ty, tx, acc);
    RESTAGE(W_hh, 192)

    // ===== u9: + XH @ W_hh_r -> B1 = r =====
    gemm4<false>(XH, WD, ty, tx, acc);
    EPI_LOOP(
        B1[o * PAD + row]       = sigm(v.x);
        B1[(o + 1) * PAD + row] = sigm(v.y);
    )
    RESTAGE(W_ih + 64, 192)

    // ===== u10: B3 @ W_ih_z =====
    init_bias(acc, b_ih + 64, b_hh + 64, tx);
    gemm4<false>(B3, WD, ty, tx, acc);
    RESTAGE(W_hh + 64, 192)

    // ===== u11: + XH @ W_hh_z -> B2 = z =====
    gemm4<false>(XH, WD, ty, tx, acc);
    EPI_LOOP(
        B2[o * PAD + row]       = sigm(v.x);
        B2[(o + 1) * PAD + row] = sigm(v.y);
    )
    RESTAGE(W_hh + 128, 192)

    // ===== u12: XH @ W_hh_n -> B4 =====
    init_bias(acc, b_hh + 128, nullptr, tx);
    gemm4<false>(XH, WD, ty, tx, acc);
    EPI_LOOP(
        B4[o * PAD + row]       = v.x;
        B4[(o + 1) * PAD + row] = v.y;
    )
    RESTAGE(W_ih + 128, 192)

    // ===== u13: B3 @ W_ih_n -> n, h_next -> B1 =====
    init_bias(acc, b_ih + 128, nullptr, tx);
    gemm4<false>(B3, WD, ty, tx, acc);
    EPI_LOOP(
        float hnx = B4[o * PAD + row];
        float hny = B4[(o + 1) * PAD + row];
        float rrx = B1[o * PAD + row];
        float rry = B1[(o + 1) * PAD + row];
        float zzx = B2[o * PAD + row];
        float zzy = B2[(o + 1) * PAD + row];
        float hvx = XH[o * PAD + row];
        float hvy = XH[(o + 1) * PAD + row];
        float nx = tanhf(v.x + rrx * hnx);
        float ny = tanhf(v.y + rry * hny);
        B1[o * PAD + row]       = (1.f - zzx) * nx + zzx * hvx;
        B1[(o + 1) * PAD + row] = (1.f - zzy) * ny + zzy * hvy;
    )
    __syncthreads();

    // ===== readout: y = sigm(h_next @ Wp + bp) =====
    {
        int row = t >> 1, half = t & 1;
        float s = 0.f;
        const float* hb = B1 + half * 32 * PAD + row;
#pragma unroll
        for (int o = 0; o < 32; ++o)
            s += hb[o * PAD] * __ldg(Wp + half * 32 + o);
        s += __shfl_xor_sync(0xffffffffu, s, 1);
        if (half == 0)
            out[row0 + row] = sigm(s + __ldg(bp));
    }
}

extern "C" void kernel_launch(void* const* d_in, const int* in_sizes, int n_in,
                              void* d_out, int out_size) {
    const int*   qt     = (const int*)  d_in[1];
    const float* ht     = (const float*)d_in[2];
    const float* onehot = (const float*)d_in[3];
    const float* kc     = (const float*)d_in[4];
    const float* graphs = (const float*)d_in[5];
    const float* nw     = (const float*)d_in[6];
    const float* Ws1    = (const float*)d_in[7];
    const float* bs1    = (const float*)d_in[8];
    const float* Ws2    = (const float*)d_in[9];
    const float* bs2    = (const float*)d_in[10];
    const float* Wn1    = (const float*)d_in[11];
    const float* bn1    = (const float*)d_in[12];
    const float* Wn2    = (const float*)d_in[13];
    const float* bn2    = (const float*)d_in[14];
    const float* ea_w   = (const float*)d_in[15];
    const float* We     = (const float*)d_in[16];
    const float* be     = (const float*)d_in[17];
    const float* Wa     = (const float*)d_in[18];
    const float* ba     = (const float*)d_in[19];
    const float* W_ih   = (const float*)d_in[20];
    const float* b_ih   = (const float*)d_in[21];
    const float* W_hh   = (const float*)d_in[22];
    const float* b_hh   = (const float*)d_in[23];
    const float* Wp     = (const float*)d_in[24];
    const float* bp     = (const float*)d_in[25];
    float* out = (float*)d_out;

    gkt_adj<<<1, 1024>>>(qt, onehot, graphs);

    const int smem_bytes = SM_TOT * (int)sizeof(float);   // 103424 B
    cudaFuncSetAttribute(gkt_main, cudaFuncAttributeMaxDynamicSharedMemorySize, smem_bytes);
    const int nrows = 256 * C_DIM;
    gkt_main<<<nrows / TILE_R, TPB, smem_bytes>>>(
        qt, ht, onehot, kc, nw,
        Ws1, bs1, Ws2, bs2, Wn1, bn1, Wn2, bn2,
        ea_w, We, be, Wa, ba, W_ih, b_ih, W_hh, b_hh, Wp, bp,
        out);
}

// round 15
// speedup vs baseline: 1.0898x; 1.0898x over previous
#include <cuda_runtime.h>

typedef unsigned long long ull;

#define C_DIM 1024
#define TPB   256
#define TILE_R 128
#define PAD  132           // row stride (floats); %4==0 for LDS.128 alignment

// smem arena layout (floats)
#define SM_X   0                        // [128][PAD] RAW x transposed: k 0..63 = ht, 64..127 = kc
#define SM_WD  (128*PAD)                // [64][64] weight tile
#define SM_B1  (SM_WD + 4096)
#define SM_B2  (SM_B1 + 64*PAD)
#define SM_B3  (SM_B2 + 64*PAD)
#define SM_TOT (SM_B3 + 64*PAD)         // 46336 floats = 185344 B

__device__ float g_adj[2 * C_DIM];
__device__ float g_kc[2 * C_DIM * 64];  // batch-invariant kc @ Wn1[k]_hi contribution

__device__ __forceinline__ float4 ldg4(const float* p) {
    return __ldg(reinterpret_cast<const float4*>(p));
}
__device__ __forceinline__ float clipf(float v, float lo, float hi) {
    return fminf(fmaxf(v, lo), hi);
}
__device__ __forceinline__ float sigm(float x) { return 1.f / (1.f + expf(-x)); }

__device__ __forceinline__ void ffma2(ull& d, ull a, ull b) {
    asm("fma.rn.f32x2 %0, %1, %2, %0;" : "+l"(d) : "l"(a), "l"(b));
}
__device__ __forceinline__ ull pk(float x, float y) {
    ull v; asm("mov.b64 %0, {%1, %2};" : "=l"(v) : "f"(x), "f"(y)); return v;
}
__device__ __forceinline__ float2 upk(ull v) {
    float2 r; asm("mov.b64 {%0, %1}, %2;" : "=f"(r.x), "=f"(r.y) : "l"(v)); return r;
}

// ---------------------------------------------------------------------------
// adj pre-kernel
// ---------------------------------------------------------------------------
__global__ void gkt_adj(const int* __restrict__ qt, const float* __restrict__ onehot,
                        const float* __restrict__ graphs) {
    __shared__ int nz[C_DIM];
    __shared__ int wcnt[32];
    __shared__ int woff[33];
    const int t = threadIdx.x, wid = t >> 5, lane = t & 31;
    const int q0 = qt[0];
    const bool on = (onehot[(long)q0 * C_DIM + t] > 0.5f);
    unsigned bal = __ballot_sync(0xffffffffu, on);
    if (lane == 0) wcnt[wid] = __popc(bal);
    __syncthreads();
    if (t == 0) { int s = 0; for (int w = 0; w < 32; ++w) { woff[w] = s; s += wcnt[w]; } woff[32] = s; }
    __syncthreads();
    if (on) nz[woff[wid] + __popc(bal & ((1u << lane) - 1u))] = t;
    __syncthreads();
    const int n = woff[32];
    const float denom = fmaxf((float)n, 1.f);
#pragma unroll
    for (int k = 0; k < 2; ++k) {
        float s = 0.f;
        for (int idx = 0; idx < n; ++idx)
            s += graphs[k * C_DIM * C_DIM + nz[idx] * C_DIM + t];
        g_adj[k * C_DIM + t] = clipf(s / denom, -5.f, 5.f);
    }
}

// ---------------------------------------------------------------------------
// kc pre-kernel: g_kc[k][c][o] = sum_j clip5(kc[c][j]) * Wn1[k][192+j][o]
// grid (16, 2), block 256
// ---------------------------------------------------------------------------
__global__ void gkt_kc(const float* __restrict__ kc, const float* __restrict__ Wn1) {
    __shared__ float Wsm[64 * 64];
    __shared__ float kcs[64 * 65];      // [j][c], padded
    const int t  = threadIdx.x;
    const int kk = blockIdx.y;
    const int c0 = blockIdx.x * 64;

    for (int i = t; i < 64 * 16; i += 256) {
        int j = i >> 4, o4 = i & 15;
        *reinterpret_cast<float4*>(Wsm + j * 64 + o4 * 4) =
            ldg4(Wn1 + (kk * 256 + 192 + j) * 64 + o4 * 4);
    }
    for (int i = t; i < 64 * 64; i += 256) {
        int c = i >> 6, j = i & 63;
        kcs[j * 65 + c] = clipf(kc[(c0 + c) * 64 + j], -5.f, 5.f);
    }
    __syncthreads();

    const int c  = t >> 2;              // 0..63
    const int ob = (t & 3) * 16;        // 16 outputs
    float acc[16];
#pragma unroll
    for (int u = 0; u < 16; ++u) acc[u] = 0.f;
#pragma unroll 4
    for (int j = 0; j < 64; ++j) {
        float kv = kcs[j * 65 + c];
#pragma unroll
        for (int u = 0; u < 16; ++u) acc[u] += kv * Wsm[j * 64 + ob + u];
    }
    float* dst = g_kc + (kk * C_DIM + c0 + c) * 64 + ob;
#pragma unroll
    for (int u = 0; u < 16; ++u) dst[u] = acc[u];
}

// ---------------------------------------------------------------------------
// helpers
// ---------------------------------------------------------------------------
__device__ __forceinline__ void stage_w(float* __restrict__ WD, const float* __restrict__ src,
                                        int rstride, int t) {
#pragma unroll
    for (int i = t; i < 64 * 16; i += TPB) {
        int kk = i >> 4, o4 = i & 15;
        *reinterpret_cast<float4*>(WD + kk * 64 + o4 * 4) = ldg4(src + kk * rstride + o4 * 4);
    }
}

// acc += A(4 rows) x W(8 outs): per k-step 1 LDS.128 (rows) + 2 LDS.128 (weights) + 16 FFMA2.
template<bool CLIP>
__device__ __forceinline__ void gemm4(const float* __restrict__ A, const float* __restrict__ WD,
                                      int ty, int tx, ull acc[16]) {
    const float* Ab = A + ty * 4;
    const ulonglong2* Wb = reinterpret_cast<const ulonglong2*>(WD) + tx;   // row = 16 u2
#pragma unroll 4
    for (int kk = 0; kk < 64; ++kk) {
        float4 av = *reinterpret_cast<const float4*>(Ab + kk * PAD);
        if (CLIP) {
            av.x = clipf(av.x, -5.f, 5.f); av.y = clipf(av.y, -5.f, 5.f);
            av.z = clipf(av.z, -5.f, 5.f); av.w = clipf(av.w, -5.f, 5.f);
        }
        ull ad[4] = { pk(av.x, av.x), pk(av.y, av.y), pk(av.z, av.z), pk(av.w, av.w) };
        ulonglong2 w0 = Wb[kk * 16];
        ulonglong2 w1 = Wb[kk * 16 + 8];
#pragma unroll
        for (int r = 0; r < 4; ++r) {
            ffma2(acc[r * 4 + 0], ad[r], w0.x);
            ffma2(acc[r * 4 + 1], ad[r], w0.y);
            ffma2(acc[r * 4 + 2], ad[r], w1.x);
            ffma2(acc[r * 4 + 3], ad[r], w1.y);
        }
    }
}

__device__ __forceinline__ void init_bias(ull acc[16], const float* __restrict__ b1p,
                                          const float* __restrict__ b2p, int tx) {
#pragma unroll
    for (int g = 0; g < 2; ++g)
#pragma unroll
    for (int p = 0; p < 2; ++p) {
        int o = 4 * tx + 32 * g + 2 * p;
        float vx = __ldg(b1p + o), vy = __ldg(b1p + o + 1);
        if (b2p) { vx += __ldg(b2p + o); vy += __ldg(b2p + o + 1); }
        ull pv = pk(vx, vy);
        acc[g * 2 + p] = pv; acc[4 + g * 2 + p] = pv;
        acc[8 + g * 2 + p] = pv; acc[12 + g * 2 + p] = pv;
    }
}

// acc init = bias[o] + g_kc[k][c0+row][o]  (per-row values)
__device__ __forceinline__ void init_bias_kc(ull acc[16], const float* __restrict__ b1p,
                                             const float* __restrict__ kcb, // g_kc + (k*C_DIM+c0)*64
                                             int tx, int ty) {
#pragma unroll
    for (int r = 0; r < 4; ++r) {
        const float* kr = kcb + (ty * 4 + r) * 64;
#pragma unroll
        for (int g = 0; g < 2; ++g)
#pragma unroll
        for (int p = 0; p < 2; ++p) {
            int o = 4 * tx + 32 * g + 2 * p;
            float2 kv = *reinterpret_cast<const float2*>(kr + o);   // via L2
            acc[r * 4 + g * 2 + p] = pk(__ldg(b1p + o) + kv.x, __ldg(b1p + o + 1) + kv.y);
        }
    }
}

#define EPI_LOOP(...)                                                          \
    _Pragma("unroll")                                                          \
    for (int r = 0; r < 4; ++r) {                                              \
        int row = ty * 4 + r;                                                  \
        _Pragma("unroll")                                                      \
        for (int g = 0; g < 2; ++g)                                            \
        _Pragma("unroll")                                                      \
        for (int p = 0; p < 2; ++p) {                                          \
            int o = 4 * tx + 32 * g + 2 * p;                                   \
            float2 v = upk(acc[r * 4 + g * 2 + p]);                            \
            __VA_ARGS__                                                        \
        }                                                                      \
    }

#define RESTAGE(SRC, RS)                                                       \
    __syncthreads();                                                           \
    stage_w(WD, (SRC), (RS), t);                                               \
    __syncthreads();

// ---------------------------------------------------------------------------
// fused main kernel: 128 rows/block, 256 threads (12 gemm units)
// ---------------------------------------------------------------------------
__global__ __launch_bounds__(TPB, 1) void gkt_main(
    const int*   __restrict__ qt,     const float* __restrict__ ht,
    const float* __restrict__ onehot, const float* __restrict__ kc,
    const float* __restrict__ nw_ptr,
    const float* __restrict__ Ws1, const float* __restrict__ bs1,
    const float* __restrict__ Ws2, const float* __restrict__ bs2,
    const float* __restrict__ Wn1, const float* __restrict__ bn1,
    const float* __restrict__ Wn2, const float* __restrict__ bn2,
    const float* __restrict__ ea_w,
    const float* __restrict__ We,  const float* __restrict__ be,
    const float* __restrict__ Wa,  const float* __restrict__ ba,
    const float* __restrict__ W_ih, const float* __restrict__ b_ih,
    const float* __restrict__ W_hh, const float* __restrict__ b_hh,
    const float* __restrict__ Wp,  const float* __restrict__ bp,
    float* __restrict__ out)
{
    extern __shared__ float sm[];
    float* X   = sm + SM_X;             // raw [ht | kc], transposed
    float* XH  = sm + SM_X;             // alias: k rows 0..63 = raw ht
    float* WD  = sm + SM_WD;
    float* B1  = sm + SM_B1;
    float* B2  = sm + SM_B2;
    float* B3  = sm + SM_B3;
    float* B4  = sm + SM_X + 64 * PAD;  // kc region, dead after fix-up
    float* tmp = B3;                    // fix-up scratch (B3 unused until u7)
    int*   mlist = (int*)(B3 + 64);
    int*   mcnt  = (int*)(B3 + 192);

    const int t  = threadIdx.x;
    const int tx = t & 7, ty = t >> 3;        // rows = ty*4 .. ty*4+3
    const int row0 = blockIdx.x * TILE_R;
    const int b  = row0 >> 10;
    const int c0 = row0 & (C_DIM - 1);
    const int q  = __ldg(&qt[b]);

    ull acc[16];
    const float wcl = clipf(__ldg(nw_ptr), 0.1f, 0.9f);

    // ---- prologue: stage raw X + first weight tile ----
#pragma unroll
    for (int i = t; i < TILE_R * 64; i += TPB) {
        int row = i >> 6, k = i & 63;
        X[k * PAD + row]        = ht[(row0 + row) * 64 + k];
        X[(64 + k) * PAD + row] = kc[(c0 + row) * 64 + k];
    }
    stage_w(WD, Wn1 + 128 * 64, 64, t);
    __syncthreads();

    // ===== v0: clip(ht) @ Wn1[0]_lo (+bias+kc0) -> B1 relu =====
    init_bias_kc(acc, bn1, g_kc + (0 * C_DIM + c0) * 64, tx, ty);
    gemm4<true>(X, WD, ty, tx, acc);
    EPI_LOOP(
        B1[o * PAD + row]       = fmaxf(v.x, 0.f);
        B1[(o + 1) * PAD + row] = fmaxf(v.y, 0.f);
    )
    RESTAGE(Wn2, 64)

    // ===== v1: B1 @ Wn2[0] -> B2 = nf0 =====
    init_bias(acc, bn2, nullptr, tx);
    gemm4<false>(B1, WD, ty, tx, acc);
    EPI_LOOP(
        float a0 = __ldg(&g_adj[c0 + row]);
        float nb0x = fminf(fmaxf(v.x, 0.f), 5.f);
        float nb0y = fminf(fmaxf(v.y, 0.f), 5.f);
        B2[o * PAD + row]       = clipf(a0 * nb0x, -5.f, 5.f);
        B2[(o + 1) * PAD + row] = clipf(a0 * nb0y, -5.f, 5.f);
    )
    RESTAGE(Wn1 + 256 * 64 + 128 * 64, 64)

    // ===== v2: clip(ht) @ Wn1[1]_lo (+bias+kc1) -> B1 relu =====
    init_bias_kc(acc, bn1 + 64, g_kc + (1 * C_DIM + c0) * 64, tx, ty);
    gemm4<true>(X, WD, ty, tx, acc);
    EPI_LOOP(
        B1[o * PAD + row]       = fmaxf(v.x, 0.f);
        B1[(o + 1) * PAD + row] = fmaxf(v.y, 0.f);
    )
    RESTAGE(Wn2 + 64 * 64, 64)

    // ===== v3: B1 @ Wn2[1] -> B2 = nf =====
    init_bias(acc, bn2 + 64, nullptr, tx);
    gemm4<false>(B1, WD, ty, tx, acc);
    EPI_LOOP(
        float a1 = __ldg(&g_adj[C_DIM + c0 + row]);
        float nb1x = fminf(fmaxf(v.x, 0.f), 5.f);
        float nb1y = fminf(fmaxf(v.y, 0.f), 5.f);
        float nf0x = B2[o * PAD + row];
        float nf0y = B2[(o + 1) * PAD + row];
        B2[o * PAD + row]       = clipf(wcl * nf0x + (1.f - wcl) * a1 * nb1x, -5.f, 5.f);
        B2[(o + 1) * PAD + row] = clipf(wcl * nf0y + (1.f - wcl) * a1 * nb1y, -5.f, 5.f);
    )
    __syncthreads();

    // ===== masked-row self-MLP fix-up (scratch in B3) =====
    if (t == 0) *mcnt = 0;
    __syncthreads();
    if (t < TILE_R) {
        float m = __ldg(&onehot[(long)q * C_DIM + c0 + t]);
        if (m > 0.5f) { int pos = atomicAdd(mcnt, 1); mlist[pos] = t; }
    }
    __syncthreads();
    const int nm = *mcnt;
    for (int idx = 0; idx < nm; ++idx) {
        int row = mlist[idx];
        if (t < 64) {
            float a = __ldg(bs1 + t);
            for (int k = 0; k < 128; ++k) a += X[k * PAD + row] * __ldg(Ws1 + k * 64 + t);
            tmp[t] = fmaxf(a, 0.f);
        }
        __syncthreads();
        if (t < 64) {
            float a = __ldg(bs2 + t);
            for (int k = 0; k < 64; ++k) a += tmp[k] * __ldg(Ws2 + k * 64 + t);
            B2[t * PAD + row] = clipf(fmaxf(a, 0.f), -10.f, 10.f);
        }
        __syncthreads();
    }
    // B2 = m_next (mn)
    stage_w(WD, We, 64, t);
    __syncthreads();

    // ===== v4: B2 @ We -> B1 = sigE =====
    init_bias(acc, be, nullptr, tx);
    gemm4<false>(B2, WD, ty, tx, acc);
    EPI_LOOP(
        B1[o * PAD + row]       = sigm(v.x);
        B1[(o + 1) * PAD + row] = sigm(v.y);
    )
    RESTAGE(Wa, 64)

    // ===== v5: B2 @ Wa -> B3 = res =====
    init_bias(acc, ba, nullptr, tx);
    gemm4<false>(B2, WD, ty, tx, acc);
    EPI_LOOP(
        float gg = __ldg(&ea_w[c0 + row]);
        float mnx = B2[o * PAD + row];
        float sgx = B1[o * PAD + row];
        float mny = B2[(o + 1) * PAD + row];
        float sgy = B1[(o + 1) * PAD + row];
        B3[o * PAD + row]       = mnx - gg * sgx * mnx + gg * tanhf(v.x);
        B3[(o + 1) * PAD + row] = mny - gg * sgy * mny + gg * tanhf(v.y);
    )
    RESTAGE(W_ih, 192)

    // ===== v6: B3 @ W_ih_r =====
    init_bias(acc, b_ih, b_hh, tx);
    gemm4<false>(B3, WD, ty, tx, acc);
    RESTAGE(W_hh, 192)

    // ===== v7: + XH @ W_hh_r -> B1 = r =====
    gemm4<false>(XH, WD, ty, tx, acc);
    EPI_LOOP(
        B1[o * PAD + row]       = sigm(v.x);
        B1[(o + 1) * PAD + row] = sigm(v.y);
    )
    RESTAGE(W_ih + 64, 192)

    // ===== v8: B3 @ W_ih_z =====
    init_bias(acc, b_ih + 64, b_hh + 64, tx);
    gemm4<false>(B3, WD, ty, tx, acc);
    RESTAGE(W_hh + 64, 192)

    // ===== v9: + XH @ W_hh_z -> B2 = z =====
    gemm4<false>(XH, WD, ty, tx, acc);
    EPI_LOOP(
        B2[o * PAD + row]       = sigm(v.x);
        B2[(o + 1) * PAD + row] = sigm(v.y);
    )
    RESTAGE(W_hh + 128, 192)

    // ===== v10: XH @ W_hh_n -> B4 =====
    init_bias(acc, b_hh + 128, nullptr, tx);
    gemm4<false>(XH, WD, ty, tx, acc);
    EPI_LOOP(
        B4[o * PAD + row]       = v.x;
        B4[(o + 1) * PAD + row] = v.y;
    )
    RESTAGE(W_ih + 128, 192)

    // ===== v11: B3 @ W_ih_n -> n, h_next -> B1 =====
    init_bias(acc, b_ih + 128, nullptr, tx);
    gemm4<false>(B3, WD, ty, tx, acc);
    EPI_LOOP(
        float hnx = B4[o * PAD + row];
        float hny = B4[(o + 1) * PAD + row];
        float rrx = B1[o * PAD + row];
        float rry = B1[(o + 1) * PAD + row];
        float zzx = B2[o * PAD + row];
        float zzy = B2[(o + 1) * PAD + row];
        float hvx = XH[o * PAD + row];
        float hvy = XH[(o + 1) * PAD + row];
        float nx = tanhf(v.x + rrx * hnx);
        float ny = tanhf(v.y + rry * hny);
        B1[o * PAD + row]       = (1.f - zzx) * nx + zzx * hvx;
        B1[(o + 1) * PAD + row] = (1.f - zzy) * ny + zzy * hvy;
    )
    __syncthreads();

    // ===== readout: y = sigm(h_next @ Wp + bp) =====
    {
        int row = t >> 1, half = t & 1;
        float s = 0.f;
        const float* hb = B1 + half * 32 * PAD + row;
#pragma unroll
        for (int o = 0; o < 32; ++o)
            s += hb[o * PAD] * __ldg(Wp + half * 32 + o);
        s += __shfl_xor_sync(0xffffffffu, s, 1);
        if (half == 0)
            out[row0 + row] = sigm(s + __ldg(bp));
    }
}

extern "C" void kernel_launch(void* const* d_in, const int* in_sizes, int n_in,
                              void* d_out, int out_size) {
    const int*   qt     = (const int*)  d_in[1];
    const float* ht     = (const float*)d_in[2];
    const float* onehot = (const float*)d_in[3];
    const float* kc     = (const float*)d_in[4];
    const float* graphs = (const float*)d_in[5];
    const float* nw     = (const float*)d_in[6];
    const float* Ws1    = (const float*)d_in[7];
    const float* bs1    = (const float*)d_in[8];
    const float* Ws2    = (const float*)d_in[9];
    const float* bs2    = (const float*)d_in[10];
    const float* Wn1    = (const float*)d_in[11];
    const float* bn1    = (const float*)d_in[12];
    const float* Wn2    = (const float*)d_in[13];
    const float* bn2    = (const float*)d_in[14];
    const float* ea_w   = (const float*)d_in[15];
    const float* We     = (const float*)d_in[16];
    const float* be     = (const float*)d_in[17];
    const float* Wa     = (const float*)d_in[18];
    const float* ba     = (const float*)d_in[19];
    const float* W_ih   = (const float*)d_in[20];
    const float* b_ih   = (const float*)d_in[21];
    const float* W_hh   = (const float*)d_in[22];
    const float* b_hh   = (const float*)d_in[23];
    const float* Wp     = (const float*)d_in[24];
    const float* bp     = (const float*)d_in[25];
    float* out = (float*)d_out;

    gkt_adj<<<1, 1024>>>(qt, onehot, graphs);
    gkt_kc<<<dim3(16, 2), 256>>>(kc, Wn1);

    const int smem_bytes = SM_TOT * (int)sizeof(float);   // 185344 B
    cudaFuncSetAttribute(gkt_main, cudaFuncAttributeMaxDynamicSharedMemorySize, smem_bytes);
    const int nrows = 256 * C_DIM;
    gkt_main<<<nrows / TILE_R, TPB, smem_bytes>>>(
        qt, ht, onehot, kc, nw,
        Ws1, bs1, Ws2, bs2, Wn1, bn1, Wn2, bn2,
        ea_w, We, be, Wa, ba, W_ih, b_ih, W_hh, b_hh, Wp, bp,
        out);
}